// round 1
// baseline (speedup 1.0000x reference)
#include <cuda_runtime.h>
#include <cstdint>

// Problem shape (fixed by the dataset)
#define M_DIM 16384
#define N_DIM 8192
#define K_DIM 64

// Tiling
#define BM 64          // output rows per CTA
#define BN 64          // n-chunk per mainloop iteration
#define THREADS 128

#define PHI_LD 68      // padded row (floats) for phi tile  [BN][PHI_LD], 68*4=272B (16B aligned)
#define W_LD 132       // padded row (floats) for duplicated W tile [BN][W_LD], 132*4=528B (16B aligned)
#define SMEM_FLOATS (BN * PHI_LD + BN * W_LD)   // 4352 + 8448 = 12800 floats = 51200 B

__device__ __forceinline__ unsigned long long ffma2(unsigned long long a,
                                                    unsigned long long b,
                                                    unsigned long long c) {
    unsigned long long d;
    asm("fma.rn.f32x2 %0, %1, %2, %3;" : "=l"(d) : "l"(a), "l"(b), "l"(c));
    return d;
}

__device__ __forceinline__ float fast_sqrt(float x) {
    float r;
    asm("sqrt.approx.f32 %0, %1;" : "=f"(r) : "f"(x));
    return r;
}

__global__ __launch_bounds__(THREADS)
void rbf_mq_kernel(const float* __restrict__ Xp,
                   const float* __restrict__ X,
                   const float* __restrict__ W,
                   const float* __restrict__ epsp,
                   float* __restrict__ out) {
    extern __shared__ float smem[];
    float* phi_s = smem;                  // [BN][PHI_LD]  phi tile, m-contiguous rows
    float* w_s   = smem + BN * PHI_LD;    // [BN][W_LD]    W tile, each w duplicated (w,w)

    const int tid = threadIdx.x;
    const int m0  = blockIdx.x * BM;

    const float eps = *epsp;
    const float e2  = eps * eps;

    // ---- phi-phase identity: this thread owns one m-row of the CTA tile ----
    const int mphi  = tid & 63;        // m within tile
    const int nbase = tid >> 6;        // 0 or 1; covers n = nbase + 2*i
    const float xpx = Xp[(m0 + mphi) * 3 + 0];
    const float xpy = Xp[(m0 + mphi) * 3 + 1];
    const float xpz = Xp[(m0 + mphi) * 3 + 2];

    // ---- matmul identity: 8 m's (4 pairs) x 4 k's per thread ----
    const int tx = tid & 15;           // k-group: k = tx*4 + j
    const int ty = tid >> 4;           // m-group: m_local = ty*8 + (0..7)

    unsigned long long acc[4][4];
#pragma unroll
    for (int i = 0; i < 4; i++)
#pragma unroll
        for (int j = 0; j < 4; j++) acc[i][j] = 0ull;

    for (int n0 = 0; n0 < N_DIM; n0 += BN) {
        __syncthreads();   // previous matmul phase done reading smem

        // Load W tile (K_DIM x BN), store duplicated so LDS.128 yields (w0,w0,w1,w1)
#pragma unroll
        for (int i = 0; i < (K_DIM * BN) / THREADS; i++) {   // 32 iterations
            int idx = tid + i * THREADS;
            int k   = idx >> 6;        // idx / BN
            int nn  = idx & 63;        // idx % BN
            float w = W[k * N_DIM + n0 + nn];
            w_s[nn * W_LD + 2 * k]     = w;
            w_s[nn * W_LD + 2 * k + 1] = w;
        }

        // Compute phi tile: phi = sqrt(eps^2 * ||xp - x||^2 + 1)
        // Direct sum of squares is >= 0, so reference's max(d2,0) is subsumed.
#pragma unroll 4
        for (int i = 0; i < BN / 2; i++) {   // 32 phis per thread
            int nn = nbase + 2 * i;
            const float* xr = &X[(size_t)(n0 + nn) * 3];
            float dx = xpx - xr[0];
            float dy = xpy - xr[1];
            float dz = xpz - xr[2];
            float d2 = fmaf(dx, dx, fmaf(dy, dy, dz * dz));
            phi_s[nn * PHI_LD + mphi] = fast_sqrt(fmaf(d2, e2, 1.0f));
        }
        __syncthreads();

        // Matmul phase: acc[m-pair][k] += phi_pair * (w,w)
#pragma unroll 8
        for (int nn = 0; nn < BN; nn++) {
            const float* prow = &phi_s[nn * PHI_LD + ty * 8];
            const float* wrow = &w_s[nn * W_LD + tx * 8];
            ulonglong2 p01 = *reinterpret_cast<const ulonglong2*>(prow);
            ulonglong2 p23 = *reinterpret_cast<const ulonglong2*>(prow + 4);
            ulonglong2 w01 = *reinterpret_cast<const ulonglong2*>(wrow);
            ulonglong2 w23 = *reinterpret_cast<const ulonglong2*>(wrow + 4);
            unsigned long long pp[4] = {p01.x, p01.y, p23.x, p23.y};
            unsigned long long ww[4] = {w01.x, w01.y, w23.x, w23.y};
#pragma unroll
            for (int i = 0; i < 4; i++)
#pragma unroll
                for (int j = 0; j < 4; j++)
                    acc[i][j] = ffma2(pp[i], ww[j], acc[i][j]);
        }
    }

    // Write out: pair i covers rows (ty*8 + 2i, ty*8 + 2i + 1), cols tx*4 .. tx*4+3
#pragma unroll
    for (int i = 0; i < 4; i++) {
        float4 lo, hi;
        float* lp = reinterpret_cast<float*>(&lo);
        float* hp = reinterpret_cast<float*>(&hi);
#pragma unroll
        for (int j = 0; j < 4; j++) {
            lp[j] = __int_as_float((unsigned)(acc[i][j] & 0xffffffffull));
            hp[j] = __int_as_float((unsigned)(acc[i][j] >> 32));
        }
        int m = m0 + ty * 8 + 2 * i;
        *reinterpret_cast<float4*>(&out[(size_t)m * K_DIM + tx * 4])       = lo;
        *reinterpret_cast<float4*>(&out[(size_t)(m + 1) * K_DIM + tx * 4]) = hi;
    }
}

extern "C" void kernel_launch(void* const* d_in, const int* in_sizes, int n_in,
                              void* d_out, int out_size) {
    const float* Xp  = (const float*)d_in[0];
    const float* X   = (const float*)d_in[1];
    const float* W   = (const float*)d_in[2];
    const float* eps = (const float*)d_in[3];
    float* out = (float*)d_out;

    const int smem_bytes = SMEM_FLOATS * sizeof(float);   // 51200 B > 48KB default
    cudaFuncSetAttribute(rbf_mq_kernel,
                         cudaFuncAttributeMaxDynamicSharedMemorySize, smem_bytes);

    dim3 grid(M_DIM / BM);   // 256 CTAs
    rbf_mq_kernel<<<grid, THREADS, smem_bytes>>>(Xp, X, W, eps, out);
}

// round 3
// speedup vs baseline: 1.7213x; 1.7213x over previous
#include <cuda_runtime.h>
#include <cstdint>

#define M_DIM 16384
#define N_DIM 8192
#define K_DIM 64

#define THREADS 128
#define M_CTA 128          // m rows per CTA (64 m-groups x 2)
#define SUBN 128           // n staged per sub-tile
#define NSPLIT 4
#define NRANGE (N_DIM / NSPLIT)   // 2048
#define WT_LD 68           // padded row (floats) for wT tile

typedef unsigned long long ull;

// ---- scratch (static device allocations are allowed) ----
__device__ float g_WT[N_DIM * K_DIM];              // W transposed: [n][k], 2MB
__device__ float g_part[NSPLIT][M_DIM * K_DIM];    // partial outputs, 16MB

// ---- f32x2 helpers ----
__device__ __forceinline__ ull ffma2(ull a, ull b, ull c) {
    ull d; asm("fma.rn.f32x2 %0, %1, %2, %3;" : "=l"(d) : "l"(a), "l"(b), "l"(c)); return d;
}
__device__ __forceinline__ ull fadd2(ull a, ull b) {
    ull d; asm("add.rn.f32x2 %0, %1, %2;" : "=l"(d) : "l"(a), "l"(b)); return d;
}
__device__ __forceinline__ ull fmul2(ull a, ull b) {
    ull d; asm("mul.rn.f32x2 %0, %1, %2;" : "=l"(d) : "l"(a), "l"(b)); return d;
}
__device__ __forceinline__ ull pack2(float lo, float hi) {
    ull d; asm("mov.b64 %0, {%1, %2};" : "=l"(d) : "f"(lo), "f"(hi)); return d;
}
__device__ __forceinline__ ull splat2(float v) {
    ull d; asm("mov.b64 %0, {%1, %1};" : "=l"(d) : "f"(v)); return d;
}
__device__ __forceinline__ void unpack2(ull p, float& lo, float& hi) {
    asm("mov.b64 {%0, %1}, %2;" : "=f"(lo), "=f"(hi) : "l"(p));
}
__device__ __forceinline__ float fast_sqrt(float x) {
    float r; asm("sqrt.approx.f32 %0, %1;" : "=f"(r) : "f"(x)); return r;
}

// ---- kernel 1: transpose W [K][N] -> g_WT [N][K] ----
__global__ __launch_bounds__(256)
void transpose_w(const float* __restrict__ W) {
    int idx = blockIdx.x * 256 + threadIdx.x;     // idx = n*64 + k
    int n = idx >> 6;
    int k = idx & 63;
    g_WT[idx] = W[k * N_DIM + n];
}

// ---- kernel 2: main fused RBF-matmul, phi in registers ----
__global__ __launch_bounds__(THREADS)
void rbf_main(const float* __restrict__ Xp,
              const float* __restrict__ X,
              const float* __restrict__ epsp) {
    __shared__ float wt[SUBN * WT_LD];   // [nn][68]  (34816 B)
    __shared__ float4 xs[SUBN];          // negated X coords (2048 B)

    const int tid = threadIdx.x;
    const int mg  = tid & 63;            // m-group
    const int kg  = tid >> 6;            // k-half: 0 or 1
    const int m0  = blockIdx.x * M_CTA + mg * 2;
    const int ns  = blockIdx.y;
    const int n_begin = ns * NRANGE;

    const float eps = *epsp;
    const ull e2p  = splat2(eps * eps);
    const ull onep = splat2(1.0f);

    // Pre-pack Xp coords for the thread's (m0, m0+1) pair
    const ull px = pack2(Xp[m0 * 3 + 0], Xp[(m0 + 1) * 3 + 0]);
    const ull py = pack2(Xp[m0 * 3 + 1], Xp[(m0 + 1) * 3 + 1]);
    const ull pz = pack2(Xp[m0 * 3 + 2], Xp[(m0 + 1) * 3 + 2]);

    ull acc0[16], acc1[16];
#pragma unroll
    for (int i = 0; i < 16; i++) { acc0[i] = 0ull; acc1[i] = 0ull; }

    for (int n0 = n_begin; n0 < n_begin + NRANGE; n0 += SUBN) {
        __syncthreads();

        // Stage W^T sub-tile: straight float4 copy (coalesced LDG, conflict-free STS)
#pragma unroll
        for (int i = 0; i < (SUBN * 16) / THREADS; i++) {   // 16 iters
            int idx = i * THREADS + tid;
            int g   = idx & 15;          // 16B group within row
            int nn  = idx >> 4;
            float4 v = *reinterpret_cast<const float4*>(&g_WT[(size_t)(n0 + nn) * K_DIM + g * 4]);
            *reinterpret_cast<float4*>(&wt[nn * WT_LD + g * 4]) = v;
        }
        // Stage negated X coords, one float4 per nn
        {
            int nn = tid;
            const float* xr = &X[(size_t)(n0 + nn) * 3];
            xs[nn] = make_float4(-xr[0], -xr[1], -xr[2], 0.0f);
        }
        __syncthreads();

        // Mainloop: fma-bound. 32 FFMA2 + 7 f32x2 phi ops per n per thread.
#pragma unroll 2
        for (int nn = 0; nn < SUBN; nn++) {
            float4 xv = xs[nn];                       // broadcast LDS.128
            ull dx = fadd2(px, splat2(xv.x));
            ull dy = fadd2(py, splat2(xv.y));
            ull dz = fadd2(pz, splat2(xv.z));
            ull d2 = ffma2(dx, dx, ffma2(dy, dy, fmul2(dz, dz)));
            ull tt = ffma2(d2, e2p, onep);
            float t0, t1; unpack2(tt, t0, t1);
            ull ph0 = splat2(fast_sqrt(t0));
            ull ph1 = splat2(fast_sqrt(t1));

            const float* wrow = &wt[nn * WT_LD + kg * 32];
#pragma unroll
            for (int q = 0; q < 4; q++) {             // 4 x (2 LDS.128 -> 8 FFMA2 x2)
                ulonglong2 wa = *reinterpret_cast<const ulonglong2*>(wrow + q * 8);
                acc0[q * 4 + 0] = ffma2(ph0, wa.x, acc0[q * 4 + 0]);
                acc1[q * 4 + 0] = ffma2(ph1, wa.x, acc1[q * 4 + 0]);
                acc0[q * 4 + 1] = ffma2(ph0, wa.y, acc0[q * 4 + 1]);
                acc1[q * 4 + 1] = ffma2(ph1, wa.y, acc1[q * 4 + 1]);
                ulonglong2 wb = *reinterpret_cast<const ulonglong2*>(wrow + q * 8 + 4);
                acc0[q * 4 + 2] = ffma2(ph0, wb.x, acc0[q * 4 + 2]);
                acc1[q * 4 + 2] = ffma2(ph1, wb.x, acc1[q * 4 + 2]);
                acc0[q * 4 + 3] = ffma2(ph0, wb.y, acc0[q * 4 + 3]);
                acc1[q * 4 + 3] = ffma2(ph1, wb.y, acc1[q * 4 + 3]);
            }
        }
    }

    // Epilogue: write partial results (k-contiguous pairs)
    float* p0 = &g_part[ns][(size_t)m0 * K_DIM + kg * 32];
    float* p1 = &g_part[ns][(size_t)(m0 + 1) * K_DIM + kg * 32];
#pragma unroll
    for (int kp = 0; kp < 16; kp++) {
        float a, b;
        unpack2(acc0[kp], a, b);
        *reinterpret_cast<float2*>(p0 + 2 * kp) = make_float2(a, b);
        unpack2(acc1[kp], a, b);
        *reinterpret_cast<float2*>(p1 + 2 * kp) = make_float2(a, b);
    }
}

// ---- kernel 3: reduce NSPLIT partials into out ----
__global__ __launch_bounds__(256)
void reduce_parts(float* __restrict__ out) {
    int i = blockIdx.x * 256 + threadIdx.x;      // float4 index
    float4 a = reinterpret_cast<const float4*>(g_part[0])[i];
    float4 b = reinterpret_cast<const float4*>(g_part[1])[i];
    float4 c = reinterpret_cast<const float4*>(g_part[2])[i];
    float4 d = reinterpret_cast<const float4*>(g_part[3])[i];
    float4 r;
    r.x = (a.x + b.x) + (c.x + d.x);
    r.y = (a.y + b.y) + (c.y + d.y);
    r.z = (a.z + b.z) + (c.z + d.z);
    r.w = (a.w + b.w) + (c.w + d.w);
    reinterpret_cast<float4*>(out)[i] = r;
}

extern "C" void kernel_launch(void* const* d_in, const int* in_sizes, int n_in,
                              void* d_out, int out_size) {
    const float* Xp  = (const float*)d_in[0];
    const float* X   = (const float*)d_in[1];
    const float* W   = (const float*)d_in[2];
    const float* eps = (const float*)d_in[3];
    float* out = (float*)d_out;

    transpose_w<<<(N_DIM * K_DIM) / 256, 256>>>(W);

    dim3 grid(M_DIM / M_CTA, NSPLIT);    // 128 x 4 = 512 CTAs
    rbf_main<<<grid, THREADS>>>(Xp, X, eps);

    reduce_parts<<<(M_DIM * K_DIM / 4) / 256, 256>>>(out);
}

// round 5
// speedup vs baseline: 3.7822x; 2.1973x over previous
#include <cuda_runtime.h>
#include <cuda_bf16.h>
#include <cstdint>

#define M_DIM 16384
#define N_DIM 8192
#define K_DIM 64

#define THREADS 128            // 4 warps
#define M_CTA 128              // warp covers 32 m
#define NSPLIT 2
#define NRANGE (N_DIM / NSPLIT)      // 4096
#define NSTEPS (NRANGE / 16)         // 256 per CTA

typedef unsigned long long ull;

// ---- device scratch ----
// B fragments, mma-ready: u32 index = ((s*4 + ktp)*2 + h)*128 + lane*4 + j
//   s: n-step (0..511), ktp: k-tile pair (0..3), h: hi/lo, lane: 0..31,
//   j: {kt_even b0, kt_even b1, kt_odd b0, kt_odd b1}
__device__ uint32_t g_Bfrag[512 * 4 * 2 * 128];          // 2MB
__device__ float g_Xpk[(N_DIM / 2) * 8];                 // per n-pair, eps-scaled, negated
__device__ float g_part[NSPLIT][M_DIM * K_DIM];          // partials, 8MB

// ---- helpers ----
__device__ __forceinline__ ull ffma2(ull a, ull b, ull c) {
    ull d; asm("fma.rn.f32x2 %0, %1, %2, %3;" : "=l"(d) : "l"(a), "l"(b), "l"(c)); return d;
}
__device__ __forceinline__ ull fadd2(ull a, ull b) {
    ull d; asm("add.rn.f32x2 %0, %1, %2;" : "=l"(d) : "l"(a), "l"(b)); return d;
}
__device__ __forceinline__ ull splat2(float v) {
    ull d; asm("mov.b64 %0, {%1, %1};" : "=l"(d) : "f"(v)); return d;
}
__device__ __forceinline__ void unpack2(ull p, float& lo, float& hi) {
    asm("mov.b64 {%0, %1}, %2;" : "=f"(lo), "=f"(hi) : "l"(p));
}
__device__ __forceinline__ float fast_sqrt(float x) {
    float r; asm("sqrt.approx.f32 %0, %1;" : "=f"(r) : "f"(x)); return r;
}
__device__ __forceinline__ void mma_bf16(float* d, uint32_t a0, uint32_t a1,
                                         uint32_t a2, uint32_t a3,
                                         uint32_t b0, uint32_t b1) {
    asm volatile(
        "mma.sync.aligned.m16n8k16.row.col.f32.bf16.bf16.f32 "
        "{%0,%1,%2,%3}, {%4,%5,%6,%7}, {%8,%9}, {%0,%1,%2,%3};"
        : "+f"(d[0]), "+f"(d[1]), "+f"(d[2]), "+f"(d[3])
        : "r"(a0), "r"(a1), "r"(a2), "r"(a3), "r"(b0), "r"(b1));
}

// ---- prep 1: X pairs, eps-scaled & negated ----
__global__ __launch_bounds__(256)
void prep_x(const float* __restrict__ X, const float* __restrict__ epsp) {
    int p = blockIdx.x * 256 + threadIdx.x;     // pair index (N/2)
    float e = *epsp;
    const float* x0 = X + (size_t)(2 * p) * 3;
    float* o = g_Xpk + (size_t)p * 8;
    o[0] = -e * x0[0]; o[1] = -e * x0[3];
    o[2] = -e * x0[1]; o[3] = -e * x0[4];
    o[4] = -e * x0[2]; o[5] = -e * x0[5];
    o[6] = 0.0f; o[7] = 0.0f;
}

// ---- prep 2: shred W into mma B fragments (hi/lo bf16 split) ----
__global__ __launch_bounds__(256)
void prep_bfrag(const float* __restrict__ W) {
    int idx = blockIdx.x * 256 + threadIdx.x;   // one u32 output
    int j   = idx & 3;
    int t   = (idx >> 2) & 31;
    int h   = (idx >> 7) & 1;
    int ktp = (idx >> 8) & 3;
    int s   = idx >> 10;

    int kt = ktp * 2 + (j >> 1);
    int km = (t & 3) * 2 + (j & 1) * 8;   // k_mma row (contraction n within step)
    int nm = t >> 2;                      // n_mma col (output k within tile)
    int kout = kt * 8 + nm;
    int n = s * 16 + km;

    float w0 = W[(size_t)kout * N_DIM + n];
    float w1 = W[(size_t)kout * N_DIM + n + 1];
    float v0, v1;
    if (h == 0) {
        v0 = __bfloat162float(__float2bfloat16(w0));
        v1 = __bfloat162float(__float2bfloat16(w1));
    } else {
        v0 = w0 - __bfloat162float(__float2bfloat16(w0));
        v1 = w1 - __bfloat162float(__float2bfloat16(w1));
    }
    uint32_t packed;
    asm("cvt.rn.bf16x2.f32 %0, %1, %2;" : "=r"(packed) : "f"(v1), "f"(v0));
    g_Bfrag[idx] = packed;
}

// ---- main kernel ----
__global__ __launch_bounds__(THREADS)
void rbf_hmma(const float* __restrict__ Xp, const float* __restrict__ epsp) {
    const int tid  = threadIdx.x;
    const int warp = tid >> 5;
    const int lane = tid & 31;
    const int ns   = blockIdx.y;
    const int mwb  = blockIdx.x * M_CTA + warp * 32;   // warp m-base
    const int s0   = ns * NSTEPS;                      // first n-step

    const float e = *epsp;
    const ull one2 = splat2(1.0f);

    // eps-scaled Xp for this thread's 4 rows: idx = tile*2 + u, row = tile*16 + u*8 + lane/4
    ull exs[4], eys[4], ezs[4];
#pragma unroll
    for (int i = 0; i < 4; i++) {
        int tile = i >> 1, u = i & 1;
        int m = mwb + tile * 16 + u * 8 + (lane >> 2);
        exs[i] = splat2(e * Xp[m * 3 + 0]);
        eys[i] = splat2(e * Xp[m * 3 + 1]);
        ezs[i] = splat2(e * Xp[m * 3 + 2]);
    }

    float acc[2][8][4];
#pragma unroll
    for (int t = 0; t < 2; t++)
#pragma unroll
        for (int k = 0; k < 8; k++)
#pragma unroll
            for (int j = 0; j < 4; j++) acc[t][k][j] = 0.0f;

    // per-thread pair pointer: pair q0 = s*8 + (lane&3), q1 = q0+4
    const float* xp = g_Xpk + ((size_t)s0 * 8 + (lane & 3)) * 8;
    const uint4* bf = reinterpret_cast<const uint4*>(g_Bfrag) + (size_t)s0 * 8 * 32 + lane;

    for (int s = 0; s < NSTEPS; s++) {
        // load both n-pair coordinate blocks (32B each)
        ulonglong2 xy0 = *reinterpret_cast<const ulonglong2*>(xp);
        ull        zz0 = *reinterpret_cast<const ull*>(xp + 4);
        ulonglong2 xy1 = *reinterpret_cast<const ulonglong2*>(xp + 32);
        ull        zz1 = *reinterpret_cast<const ull*>(xp + 36);
        xp += 64;

        // A fragments: ah[tile][areg], al[tile][areg]; areg = u + 2*pair
        uint32_t ah[2][4], al[2][4];
#pragma unroll
        for (int tile = 0; tile < 2; tile++) {
#pragma unroll
            for (int u = 0; u < 2; u++) {
                int ci = tile * 2 + u;
#pragma unroll
                for (int p = 0; p < 2; p++) {
                    ull dx = fadd2(exs[ci], p ? xy1.x : xy0.x);
                    ull dy = fadd2(eys[ci], p ? xy1.y : xy0.y);
                    ull dz = fadd2(ezs[ci], p ? zz1 : zz0);
                    ull tt = ffma2(dx, dx, ffma2(dy, dy, ffma2(dz, dz, one2)));
                    float t0, t1; unpack2(tt, t0, t1);
                    float sq0 = fast_sqrt(t0), sq1 = fast_sqrt(t1);
                    uint32_t hb;
                    asm("cvt.rn.bf16x2.f32 %0, %1, %2;" : "=r"(hb) : "f"(sq1), "f"(sq0));
                    float h0 = __uint_as_float(hb << 16);
                    float h1 = __uint_as_float(hb & 0xffff0000u);
                    float l0 = sq0 - h0, l1 = sq1 - h1;
                    uint32_t lb;
                    asm("cvt.rn.bf16x2.f32 %0, %1, %2;" : "=r"(lb) : "f"(l1), "f"(l0));
                    ah[tile][u + 2 * p] = hb;
                    al[tile][u + 2 * p] = lb;
                }
            }
        }

        // B fragments + MMAs: 4 ktp x {2 kt} x {2 tiles} x 3 terms = 48 HMMA
#pragma unroll
        for (int ktp = 0; ktp < 4; ktp++) {
            uint4 bh = __ldg(bf + ktp * 2 * 32);        // h=0
            uint4 bl = __ldg(bf + (ktp * 2 + 1) * 32);  // h=1
#pragma unroll
            for (int tile = 0; tile < 2; tile++) {
                float* a0 = acc[tile][ktp * 2];
                mma_bf16(a0, ah[tile][0], ah[tile][1], ah[tile][2], ah[tile][3], bh.x, bh.y);
                mma_bf16(a0, ah[tile][0], ah[tile][1], ah[tile][2], ah[tile][3], bl.x, bl.y);
                mma_bf16(a0, al[tile][0], al[tile][1], al[tile][2], al[tile][3], bh.x, bh.y);
                float* a1 = acc[tile][ktp * 2 + 1];
                mma_bf16(a1, ah[tile][0], ah[tile][1], ah[tile][2], ah[tile][3], bh.z, bh.w);
                mma_bf16(a1, ah[tile][0], ah[tile][1], ah[tile][2], ah[tile][3], bl.z, bl.w);
                mma_bf16(a1, al[tile][0], al[tile][1], al[tile][2], al[tile][3], bh.z, bh.w);
            }
        }
        bf += 8 * 32;
    }

    // epilogue: write partials. d0,d1 -> row r, cols c,c+1 ; d2,d3 -> row r+8
    float* part = g_part[ns];
#pragma unroll
    for (int tile = 0; tile < 2; tile++) {
        int rbase = mwb + tile * 16 + (lane >> 2);
#pragma unroll
        for (int kt = 0; kt < 8; kt++) {
            int c = kt * 8 + (lane & 3) * 2;
            *reinterpret_cast<float2*>(&part[(size_t)rbase * K_DIM + c]) =
                make_float2(acc[tile][kt][0], acc[tile][kt][1]);
            *reinterpret_cast<float2*>(&part[(size_t)(rbase + 8) * K_DIM + c]) =
                make_float2(acc[tile][kt][2], acc[tile][kt][3]);
        }
    }
}

// ---- reduce ----
__global__ __launch_bounds__(256)
void reduce_parts(float* __restrict__ out) {
    int i = blockIdx.x * 256 + threadIdx.x;
    float4 a = reinterpret_cast<const float4*>(g_part[0])[i];
    float4 b = reinterpret_cast<const float4*>(g_part[1])[i];
    reinterpret_cast<float4*>(out)[i] =
        make_float4(a.x + b.x, a.y + b.y, a.z + b.z, a.w + b.w);
}

extern "C" void kernel_launch(void* const* d_in, const int* in_sizes, int n_in,
                              void* d_out, int out_size) {
    const float* Xp  = (const float*)d_in[0];
    const float* X   = (const float*)d_in[1];
    const float* W   = (const float*)d_in[2];
    const float* eps = (const float*)d_in[3];
    float* out = (float*)d_out;

    prep_x<<<(N_DIM / 2) / 256, 256>>>(X, eps);
    prep_bfrag<<<(512 * 4 * 2 * 128) / 256, 256>>>(W);

    dim3 grid(M_DIM / M_CTA, NSPLIT);   // 128 x 2 = 256 CTAs
    rbf_hmma<<<grid, THREADS>>>(Xp, eps);

    reduce_parts<<<(M_DIM * K_DIM / 4) / 256, 256>>>(out);
}

// round 6
// speedup vs baseline: 5.6527x; 1.4946x over previous
#include <cuda_runtime.h>
#include <cuda_bf16.h>
#include <cstdint>

#define M_DIM 16384
#define N_DIM 8192
#define K_DIM 64

#define THREADS 128            // 4 warps
#define M_CTA 128              // warp covers 32 m
#define NSPLIT 4
#define NRANGE (N_DIM / NSPLIT)      // 2048
#define NSTEPS (NRANGE / 16)         // 128 per CTA

typedef unsigned long long ull;

// ---- device scratch ----
// B fragments, mma-ready: u32 index = ((s*4 + ktp)*2 + h)*128 + lane*4 + j
__device__ uint32_t g_Bfrag[512 * 4 * 2 * 128];          // 2MB
__device__ float g_Xpk[(N_DIM / 2) * 8];                 // per n-pair, eps-scaled, negated
__device__ float g_part[NSPLIT][M_DIM * K_DIM];          // partials, 16MB

// ---- helpers ----
__device__ __forceinline__ ull ffma2(ull a, ull b, ull c) {
    ull d; asm("fma.rn.f32x2 %0, %1, %2, %3;" : "=l"(d) : "l"(a), "l"(b), "l"(c)); return d;
}
__device__ __forceinline__ ull fadd2(ull a, ull b) {
    ull d; asm("add.rn.f32x2 %0, %1, %2;" : "=l"(d) : "l"(a), "l"(b)); return d;
}
__device__ __forceinline__ ull splat2(float v) {
    ull d; asm("mov.b64 %0, {%1, %1};" : "=l"(d) : "f"(v)); return d;
}
__device__ __forceinline__ void unpack2(ull p, float& lo, float& hi) {
    asm("mov.b64 {%0, %1}, %2;" : "=f"(lo), "=f"(hi) : "l"(p));
}
__device__ __forceinline__ float fast_sqrt(float x) {
    float r; asm("sqrt.approx.f32 %0, %1;" : "=f"(r) : "f"(x)); return r;
}
__device__ __forceinline__ void mma_bf16(float* d, uint32_t a0, uint32_t a1,
                                         uint32_t a2, uint32_t a3,
                                         uint32_t b0, uint32_t b1) {
    asm volatile(
        "mma.sync.aligned.m16n8k16.row.col.f32.bf16.bf16.f32 "
        "{%0,%1,%2,%3}, {%4,%5,%6,%7}, {%8,%9}, {%0,%1,%2,%3};"
        : "+f"(d[0]), "+f"(d[1]), "+f"(d[2]), "+f"(d[3])
        : "r"(a0), "r"(a1), "r"(a2), "r"(a3), "r"(b0), "r"(b1));
}

// ---- prep 1: X pairs, eps-scaled & negated ----
__global__ __launch_bounds__(256)
void prep_x(const float* __restrict__ X, const float* __restrict__ epsp) {
    int p = blockIdx.x * 256 + threadIdx.x;     // pair index (N/2)
    float e = *epsp;
    const float* x0 = X + (size_t)(2 * p) * 3;
    float* o = g_Xpk + (size_t)p * 8;
    o[0] = -e * x0[0]; o[1] = -e * x0[3];
    o[2] = -e * x0[1]; o[3] = -e * x0[4];
    o[4] = -e * x0[2]; o[5] = -e * x0[5];
    o[6] = 0.0f; o[7] = 0.0f;
}

// ---- prep 2: shred W into mma B fragments (hi/lo bf16 split) ----
__global__ __launch_bounds__(256)
void prep_bfrag(const float* __restrict__ W) {
    int idx = blockIdx.x * 256 + threadIdx.x;   // one u32 output
    int j   = idx & 3;
    int t   = (idx >> 2) & 31;
    int h   = (idx >> 7) & 1;
    int ktp = (idx >> 8) & 3;
    int s   = idx >> 10;

    int kt = ktp * 2 + (j >> 1);
    int km = (t & 3) * 2 + (j & 1) * 8;   // contraction row within step
    int nm = t >> 2;                      // output col within tile
    int kout = kt * 8 + nm;
    int n = s * 16 + km;

    float w0 = W[(size_t)kout * N_DIM + n];
    float w1 = W[(size_t)kout * N_DIM + n + 1];
    float v0, v1;
    if (h == 0) {
        v0 = __bfloat162float(__float2bfloat16(w0));
        v1 = __bfloat162float(__float2bfloat16(w1));
    } else {
        v0 = w0 - __bfloat162float(__float2bfloat16(w0));
        v1 = w1 - __bfloat162float(__float2bfloat16(w1));
    }
    uint32_t packed;
    asm("cvt.rn.bf16x2.f32 %0, %1, %2;" : "=r"(packed) : "f"(v1), "f"(v0));
    g_Bfrag[idx] = packed;
}

// ---- main kernel ----
__global__ __launch_bounds__(THREADS, 3)
void rbf_hmma(const float* __restrict__ Xp, const float* __restrict__ epsp) {
    const int tid  = threadIdx.x;
    const int warp = tid >> 5;
    const int lane = tid & 31;
    const int ns   = blockIdx.y;
    const int mwb  = blockIdx.x * M_CTA + warp * 32;   // warp m-base
    const int s0   = ns * NSTEPS;                      // first n-step

    const float e = *epsp;
    const ull one2 = splat2(1.0f);

    // eps-scaled Xp for this thread's 4 rows
    ull exs[4], eys[4], ezs[4];
#pragma unroll
    for (int i = 0; i < 4; i++) {
        int tile = i >> 1, u = i & 1;
        int m = mwb + tile * 16 + u * 8 + (lane >> 2);
        exs[i] = splat2(e * Xp[m * 3 + 0]);
        eys[i] = splat2(e * Xp[m * 3 + 1]);
        ezs[i] = splat2(e * Xp[m * 3 + 2]);
    }

    float acc[2][8][4];
#pragma unroll
    for (int t = 0; t < 2; t++)
#pragma unroll
        for (int k = 0; k < 8; k++)
#pragma unroll
            for (int j = 0; j < 4; j++) acc[t][k][j] = 0.0f;

    const float* xp = g_Xpk + ((size_t)s0 * 8 + (lane & 3)) * 8;
    const uint4* bf = reinterpret_cast<const uint4*>(g_Bfrag) + (size_t)s0 * 8 * 32 + lane;

#pragma unroll 2
    for (int s = 0; s < NSTEPS; s++) {
        // ---- issue ALL loads first: B fragments (8 x LDG.128) + coords ----
        uint4 bfr[8];
#pragma unroll
        for (int q = 0; q < 8; q++) bfr[q] = __ldg(bf + q * 32);
        bf += 8 * 32;

        ulonglong2 xy0 = *reinterpret_cast<const ulonglong2*>(xp);
        ull        zz0 = *reinterpret_cast<const ull*>(xp + 4);
        ulonglong2 xy1 = *reinterpret_cast<const ulonglong2*>(xp + 32);
        ull        zz1 = *reinterpret_cast<const ull*>(xp + 36);
        xp += 64;

        // ---- phi chain (covers load latency) ----
        uint32_t ah[2][4], al[2][4];
#pragma unroll
        for (int tile = 0; tile < 2; tile++) {
#pragma unroll
            for (int u = 0; u < 2; u++) {
                int ci = tile * 2 + u;
#pragma unroll
                for (int p = 0; p < 2; p++) {
                    ull dx = fadd2(exs[ci], p ? xy1.x : xy0.x);
                    ull dy = fadd2(eys[ci], p ? xy1.y : xy0.y);
                    ull dz = fadd2(ezs[ci], p ? zz1 : zz0);
                    ull tt = ffma2(dx, dx, ffma2(dy, dy, ffma2(dz, dz, one2)));
                    float t0, t1; unpack2(tt, t0, t1);
                    float sq0 = fast_sqrt(t0), sq1 = fast_sqrt(t1);
                    uint32_t hb;
                    asm("cvt.rn.bf16x2.f32 %0, %1, %2;" : "=r"(hb) : "f"(sq1), "f"(sq0));
                    float h0 = __uint_as_float(hb << 16);
                    float h1 = __uint_as_float(hb & 0xffff0000u);
                    float l0 = sq0 - h0, l1 = sq1 - h1;
                    uint32_t lb;
                    asm("cvt.rn.bf16x2.f32 %0, %1, %2;" : "=r"(lb) : "f"(l1), "f"(l0));
                    ah[tile][u + 2 * p] = hb;
                    al[tile][u + 2 * p] = lb;
                }
            }
        }

        // ---- MMAs: 48 HMMA per step ----
#pragma unroll
        for (int ktp = 0; ktp < 4; ktp++) {
            uint4 bh = bfr[ktp * 2];
            uint4 bl = bfr[ktp * 2 + 1];
#pragma unroll
            for (int tile = 0; tile < 2; tile++) {
                float* a0 = acc[tile][ktp * 2];
                mma_bf16(a0, ah[tile][0], ah[tile][1], ah[tile][2], ah[tile][3], bh.x, bh.y);
                mma_bf16(a0, ah[tile][0], ah[tile][1], ah[tile][2], ah[tile][3], bl.x, bl.y);
                mma_bf16(a0, al[tile][0], al[tile][1], al[tile][2], al[tile][3], bh.x, bh.y);
                float* a1 = acc[tile][ktp * 2 + 1];
                mma_bf16(a1, ah[tile][0], ah[tile][1], ah[tile][2], ah[tile][3], bh.z, bh.w);
                mma_bf16(a1, ah[tile][0], ah[tile][1], ah[tile][2], ah[tile][3], bl.z, bl.w);
                mma_bf16(a1, al[tile][0], al[tile][1], al[tile][2], al[tile][3], bh.z, bh.w);
            }
        }
    }

    // epilogue: write partials
    float* part = g_part[ns];
#pragma unroll
    for (int tile = 0; tile < 2; tile++) {
        int rbase = mwb + tile * 16 + (lane >> 2);
#pragma unroll
        for (int kt = 0; kt < 8; kt++) {
            int c = kt * 8 + (lane & 3) * 2;
            *reinterpret_cast<float2*>(&part[(size_t)rbase * K_DIM + c]) =
                make_float2(acc[tile][kt][0], acc[tile][kt][1]);
            *reinterpret_cast<float2*>(&part[(size_t)(rbase + 8) * K_DIM + c]) =
                make_float2(acc[tile][kt][2], acc[tile][kt][3]);
        }
    }
}

// ---- reduce ----
__global__ __launch_bounds__(256)
void reduce_parts(float* __restrict__ out) {
    int i = blockIdx.x * 256 + threadIdx.x;
    float4 a = reinterpret_cast<const float4*>(g_part[0])[i];
    float4 b = reinterpret_cast<const float4*>(g_part[1])[i];
    float4 c = reinterpret_cast<const float4*>(g_part[2])[i];
    float4 d = reinterpret_cast<const float4*>(g_part[3])[i];
    float4 r;
    r.x = (a.x + b.x) + (c.x + d.x);
    r.y = (a.y + b.y) + (c.y + d.y);
    r.z = (a.z + b.z) + (c.z + d.z);
    r.w = (a.w + b.w) + (c.w + d.w);
    reinterpret_cast<float4*>(out)[i] = r;
}

extern "C" void kernel_launch(void* const* d_in, const int* in_sizes, int n_in,
                              void* d_out, int out_size) {
    const float* Xp  = (const float*)d_in[0];
    const float* X   = (const float*)d_in[1];
    const float* W   = (const float*)d_in[2];
    const float* eps = (const float*)d_in[3];
    float* out = (float*)d_out;

    prep_x<<<(N_DIM / 2) / 256, 256>>>(X, eps);
    prep_bfrag<<<(512 * 4 * 2 * 128) / 256, 256>>>(W);

    dim3 grid(M_DIM / M_CTA, NSPLIT);   // 128 x 4 = 512 CTAs
    rbf_hmma<<<grid, THREADS>>>(Xp, eps);

    reduce_parts<<<(M_DIM * K_DIM / 4) / 256, 256>>>(out);
}